// round 14
// baseline (speedup 1.0000x reference)
#include <cuda_runtime.h>
#include <math.h>

#define BB 8
#define NN 8192
#define SS 2048
#define KK 32
#define CNT (BB*SS*KK)          // 524288 elements per layer
#define OUT_XYZ_ELEMS (BB*SS*3) // 49152

typedef unsigned long long ull;

// ---------------- scratch (static device memory; no runtime allocation) ----
__device__ float g_bufB[(size_t)CNT * 32];  // 64 MB : z2 (32ch), channel-major
__device__ float g_max[(size_t)BB * SS * 64]; // 4 MB : per-(b,s) max_k z3, [bs][o]
__device__ int   g_fps[BB * SS];
__device__ int   g_ball[BB * SS * KK];
__device__ float g_stats[3 * 128];          // per layer: [0..63]=sum, [64..127]=sumsq

// ---------------- packed f32x2 helpers (sm_103a) ---------------------------
__device__ __forceinline__ ull pack2(float lo, float hi) {
    ull r; asm("mov.b64 %0,{%1,%2};" : "=l"(r) : "f"(lo), "f"(hi)); return r;
}
__device__ __forceinline__ void unpack2(ull v, float& lo, float& hi) {
    asm("mov.b64 {%0,%1},%2;" : "=f"(lo), "=f"(hi) : "l"(v));
}
__device__ __forceinline__ ull add2(ull a, ull b) {
    ull r; asm("add.rn.f32x2 %0,%1,%2;" : "=l"(r) : "l"(a), "l"(b)); return r;
}
__device__ __forceinline__ ull mul2(ull a, ull b) {
    ull r; asm("mul.rn.f32x2 %0,%1,%2;" : "=l"(r) : "l"(a), "l"(b)); return r;
}
__device__ __forceinline__ ull fma2(ull a, ull b, ull c) {
    ull r; asm("fma.rn.f32x2 %0,%1,%2,%3;" : "=l"(r) : "l"(a), "l"(b), "l"(c)); return r;
}

// ============================================================================
// 1) Farthest point sampling (UNCHANGED — banked 1277us structure).
// ============================================================================
__global__ void __launch_bounds__(512) fps_kernel(const float* __restrict__ xyz)
{
    const int b = blockIdx.x;
    const float* base = xyz + (size_t)b * NN * 3;
    const int t = threadIdx.x;
    const int lane = t & 31, wid = t >> 5;

    ull px[8], py[8], pz[8];
    float dd[16];
#pragma unroll
    for (int k = 0; k < 8; k++) {
        const int p0 = t + (2 * k) * 512;
        const int p1 = t + (2 * k + 1) * 512;
        px[k] = pack2(base[3 * p0 + 0], base[3 * p1 + 0]);
        py[k] = pack2(base[3 * p0 + 1], base[3 * p1 + 1]);
        pz[k] = pack2(base[3 * p0 + 2], base[3 * p1 + 2]);
    }
#pragma unroll
    for (int j = 0; j < 16; j++) dd[j] = 1e10f;

    __shared__ unsigned sdist[16];
    __shared__ unsigned sidxs[3];
    if (t < 3) sidxs[t] = 0xffffffffu;
    __syncthreads();

    float cx = base[0], cy = base[1], cz = base[2];
    int cur = 0;
    int slot = 0, nslot = 1, rslot = 2;

    for (int it = 0; it < SS; it++) {
        if (t == 0) {
            g_fps[b * SS + it] = cur;
            sidxs[nslot] = 0xffffffffu;
        }
        const ull ncx = pack2(-cx, -cx);
        const ull ncy = pack2(-cy, -cy);
        const ull ncz = pack2(-cz, -cz);

        float m0 = 0.f, m1 = 0.f;
#pragma unroll
        for (int k = 0; k < 8; k++) {
            ull dx = add2(px[k], ncx);
            ull dy = add2(py[k], ncy);
            ull dz = add2(pz[k], ncz);
            ull d2 = mul2(dx, dx);
            d2 = fma2(dy, dy, d2);
            d2 = fma2(dz, dz, d2);
            float dlo, dhi; unpack2(d2, dlo, dhi);
            const float nlo = fminf(dd[2 * k],     dlo);
            const float nhi = fminf(dd[2 * k + 1], dhi);
            dd[2 * k]     = nlo;
            dd[2 * k + 1] = nhi;
            m0 = fmaxf(m0, nlo);
            m1 = fmaxf(m1, nhi);
        }
        const float m = fmaxf(m0, m1);
        const unsigned mb   = __float_as_uint(m);
        const unsigned wmax = __reduce_max_sync(0xffffffffu, mb);
        if (lane == 0) sdist[wid] = wmax;
        __syncthreads();

        const unsigned bmax = __reduce_max_sync(0xffffffffu, sdist[lane & 15]);

        if (wmax == bmax) {
            unsigned bi = 0xffffffffu;
            if (mb == bmax) {
#pragma unroll
                for (int j = 15; j >= 0; j--)
                    if (__float_as_uint(dd[j]) == bmax) bi = (unsigned)(t + j * 512);
            }
            const unsigned rid = __reduce_min_sync(0xffffffffu, bi);
            if (lane == 0) atomicMin(&sidxs[slot], rid);
        }
        __syncthreads();

        cur = (int)sidxs[slot];
        cx = base[3 * cur + 0];
        cy = base[3 * cur + 1];
        cz = base[3 * cur + 2];

        const int tmp = slot; slot = nslot; nslot = rslot; rslot = tmp;
    }
}

// ============================================================================
// 2) new_xyz gather + ball query, SoA smem tile + 2 points/lane packed scan.
//    Dual-ballot prefix keeps exact ascending-index collection and the
//    pos==0 first-index rule. Block 0 also zeroes g_stats.
// ============================================================================
#define TPTS 1024
__global__ void __launch_bounds__(256) bq_kernel(const float* __restrict__ xyz,
                                                 float* __restrict__ newxyz)
{
    const int tid = threadIdx.x;
    if (blockIdx.x == 0) {
        for (int i = tid; i < 384; i += 256) g_stats[i] = 0.f;
    }

    const int warp = tid >> 5, lane = tid & 31;
    const int gs = blockIdx.x * 8 + warp;
    const int b  = gs >> 11;
    const float* base = xyz + (size_t)b * NN * 3;

    __shared__ ull  spx2[TPTS / 2], spy2[TPTS / 2], spz2[TPTS / 2];
    __shared__ int  sidx[8][KK];
    __shared__ int  sdone;
    float* spx = (float*)spx2;
    float* spy = (float*)spy2;
    float* spz = (float*)spz2;
    if (tid == 0) sdone = 0;

    const int ci = g_fps[gs];
    const float cx = base[3 * ci + 0];
    const float cy = base[3 * ci + 1];
    const float cz = base[3 * ci + 2];
    if (lane < 3) newxyz[(size_t)gs * 3 + lane] = base[3 * ci + lane];

    const ull ncx = pack2(-cx, -cx);
    const ull ncy = pack2(-cy, -cy);
    const ull ncz = pack2(-cz, -cz);

    const float r2 = (float)(0.2 * 0.2);
    int cnt = 0, first = 0x7fffffff;
    bool done = false;

    for (int tile = 0; tile < NN; tile += TPTS) {
        __syncthreads();
        if (sdone == 8) break;
        for (int i = tid; i < TPTS * 3; i += 256) {   // AoS global -> SoA smem
            const float v = base[(size_t)tile * 3 + i];
            const int p = i / 3, c = i - 3 * p;
            if (c == 0) spx[p] = v; else if (c == 1) spy[p] = v; else spz[p] = v;
        }
        __syncthreads();

        if (!done) {
            for (int s = 0; s < TPTS / 64; s++) {     // 64 points per step
                const int pr = s * 32 + lane;          // pair index in tile
                ull dx = add2(spx2[pr], ncx);
                ull d2 = mul2(dx, dx);
                ull dy = add2(spy2[pr], ncy);
                d2 = fma2(dy, dy, d2);
                ull dz = add2(spz2[pr], ncz);
                d2 = fma2(dz, dz, d2);
                float d0, d1; unpack2(d2, d0, d1);
                const bool in0 = !(d0 > r2);
                const bool in1 = !(d1 > r2);
                const unsigned m0 = __ballot_sync(0xffffffffu, in0);
                const unsigned m1 = __ballot_sync(0xffffffffu, in1);
                const unsigned below = (1u << lane) - 1u;
                const int before = __popc(m0 & below) + __popc(m1 & below);
                const int pos0 = cnt + before;
                const int pos1 = pos0 + (in0 ? 1 : 0);
                const int gp0 = tile + s * 64 + 2 * lane;
                if (in0) {
                    if (pos0 < KK) sidx[warp][pos0] = gp0;
                    if (pos0 == 0) first = gp0;
                }
                if (in1) {
                    if (pos1 < KK) sidx[warp][pos1] = gp0 + 1;
                    if (pos1 == 0) first = gp0 + 1;
                }
                cnt += __popc(m0) + __popc(m1);
                if (cnt >= KK) break;                  // warp-uniform
            }
            if (cnt >= KK) {
                done = true;
                if (lane == 0) atomicAdd(&sdone, 1);
            }
        }
    }
#pragma unroll
    for (int off = 16; off > 0; off >>= 1)
        first = min(first, __shfl_down_sync(0xffffffffu, first, off));
    first = __shfl_sync(0xffffffffu, first, 0);

    const int cc = cnt < KK ? cnt : KK;
    const int v  = (lane < cc) ? sidx[warp][lane] : first;
    g_ball[(size_t)gs * KK + lane] = v;
}

// BN affine from stats
__device__ __forceinline__ void bn_affine(int L, int c,
                                          const float* __restrict__ g,
                                          const float* __restrict__ be,
                                          float& a, float& cc)
{
    const float inv  = 1.f / (float)CNT;
    const float mean = g_stats[L * 128 + c] * inv;
    const float var  = g_stats[L * 128 + 64 + c] * inv - mean * mean;
    a  = g[c] * rsqrtf(var + 1e-5f);
    cc = be[c] - mean * a;
}

// shared gather: one pair of elements' 6 input features into smem
__device__ __forceinline__ void gather_pair(int e0,
                                            const float* __restrict__ xyz,
                                            const float* __restrict__ pts,
                                            const float* __restrict__ newxyz,
                                            ull* in0, ull* in1, ull* in2_,
                                            ull* in3, ull* in4, ull* in5, int pr)
{
    const int bs = e0 >> 5;
    const int b  = bs >> 11;
    const int2 pp = *(const int2*)&g_ball[e0];
    const float* xb = xyz + (size_t)b * NN * 3;
    const float* pb = pts + (size_t)b * NN * 3;
    const float nx = newxyz[(size_t)bs * 3 + 0];
    const float ny = newxyz[(size_t)bs * 3 + 1];
    const float nz = newxyz[(size_t)bs * 3 + 2];
    in0[pr] = pack2(xb[3 * pp.x + 0] - nx, xb[3 * pp.y + 0] - nx);
    in1[pr] = pack2(xb[3 * pp.x + 1] - ny, xb[3 * pp.y + 1] - ny);
    in2_[pr] = pack2(xb[3 * pp.x + 2] - nz, xb[3 * pp.y + 2] - nz);
    in3[pr] = pack2(pb[3 * pp.x + 0], pb[3 * pp.y + 0]);
    in4[pr] = pack2(pb[3 * pp.x + 1], pb[3 * pp.y + 1]);
    in5[pr] = pack2(pb[3 * pp.x + 2], pb[3 * pp.y + 2]);
}

// ============================================================================
// 3) Layer 1, STATS-ONLY: gather, 6->32 conv in registers (same fma2 chain as
//    the l2 recompute), stats. z1 is NOT stored (recomputed in l2).
// ============================================================================
__global__ void __launch_bounds__(256) l1_kernel(const float* __restrict__ xyz,
                                                 const float* __restrict__ pts,
                                                 const float* __restrict__ w,
                                                 const float* __restrict__ bias,
                                                 const float* __restrict__ newxyz)
{
    __shared__ ull   hsm[6][128];
    __shared__ ull   swd2[192];
    __shared__ ull   sb2[32];
    __shared__ float ssum[32], ssq[32];
    const int tid = threadIdx.x;
    if (tid < 192) { float v = w[tid]; swd2[tid] = pack2(v, v); }
    if (tid < 32)  { float v = bias[tid]; sb2[tid] = pack2(v, v); }
    __syncthreads();

    const int P0 = blockIdx.x * 128;
    if (tid < 128)
        gather_pair(2 * (P0 + tid), xyz, pts, newxyz,
                    hsm[0], hsm[1], hsm[2], hsm[3], hsm[4], hsm[5], tid);
    __syncthreads();

    const int wp = tid >> 5, l = tid & 31;
    ull acc[4][4];
#pragma unroll
    for (int j = 0; j < 4; j++) {
        const ull bj = sb2[wp + 8 * j];
#pragma unroll
        for (int q = 0; q < 4; q++) acc[j][q] = bj;
    }
#pragma unroll
    for (int i = 0; i < 6; i++) {
        ull wv[4], hv[4];
#pragma unroll
        for (int j = 0; j < 4; j++) wv[j] = swd2[(wp + 8 * j) * 6 + i];
#pragma unroll
        for (int q = 0; q < 4; q++) hv[q] = hsm[i][l + 32 * q];
#pragma unroll
        for (int j = 0; j < 4; j++)
#pragma unroll
            for (int q = 0; q < 4; q++)
                acc[j][q] = fma2(wv[j], hv[q], acc[j][q]);
    }
#pragma unroll
    for (int j = 0; j < 4; j++) {
        const int c = wp + 8 * j;
        float v = 0.f, v2 = 0.f;
#pragma unroll
        for (int q = 0; q < 4; q++) {
            float lo, hi; unpack2(acc[j][q], lo, hi);
            v  += lo + hi;
            v2 += fmaf(hi, hi, lo * lo);
        }
#pragma unroll
        for (int off = 16; off > 0; off >>= 1) {
            v  += __shfl_down_sync(0xffffffffu, v,  off);
            v2 += __shfl_down_sync(0xffffffffu, v2, off);
        }
        if (l == 0) { ssum[c] = v; ssq[c] = v2; }
    }
    __syncthreads();
    if (tid < 32) {
        atomicAdd(&g_stats[0 * 128 + tid],      ssum[tid]);
        atomicAdd(&g_stats[0 * 128 + 64 + tid], ssq[tid]);
    }
}

// ============================================================================
// 4) Layer 2: RECOMPUTE z1 (bit-identical fma2 chain) -> BN1+relu staging tile
//    -> warp-per-channel-group GEMM -> z2 + stats. Dynamic smem (~49KB).
// ============================================================================
#define SMEM_L2 (32*128*8 + 6*128*8 + 1024*8 + 192*8 + 32*8*4 + 32*4*2)
__global__ void __launch_bounds__(256) l2_kernel(const float* __restrict__ xyz,
                                                 const float* __restrict__ pts,
                                                 const float* __restrict__ newxyz,
                                                 const float* __restrict__ w0,
                                                 const float* __restrict__ b0,
                                                 const float* __restrict__ w,
                                                 const float* __restrict__ bias,
                                                 const float* __restrict__ g0,
                                                 const float* __restrict__ be0)
{
    extern __shared__ char smraw[];
    ull* hsm  = (ull*)smraw;              // [32][128]
    ull* insm = hsm + 32 * 128;           // [6][128]
    ull* sw1d = insm + 6 * 128;           // [1024]
    ull* sw0d = sw1d + 1024;              // [192]
    ull* sb0  = sw0d + 192;               // [32]
    ull* sb2  = sb0 + 32;                 // [32]
    ull* sa2  = sb2 + 32;                 // [32]
    ull* sc2  = sa2 + 32;                 // [32]
    float* ssum = (float*)(sc2 + 32);     // [32]
    float* ssq  = ssum + 32;              // [32]

    const int tid = threadIdx.x;
    for (int i = tid; i < 1024; i += 256) { float v = w[i]; sw1d[i] = pack2(v, v); }
    if (tid < 192) { float v = w0[tid]; sw0d[tid] = pack2(v, v); }
    if (tid < 32) {
        float v0 = b0[tid];  sb0[tid] = pack2(v0, v0);
        float v  = bias[tid]; sb2[tid] = pack2(v, v);
        float a, c; bn_affine(0, tid, g0, be0, a, c);
        sa2[tid] = pack2(a, a); sc2[tid] = pack2(c, c);
    }
    __syncthreads();

    const int P0 = blockIdx.x * 128;
    if (tid < 128)
        gather_pair(2 * (P0 + tid), xyz, pts, newxyz,
                    insm, insm + 128, insm + 256, insm + 384, insm + 512, insm + 640, tid);
    __syncthreads();

    {   // recompute z1 (16 channels per thread), BN1+relu -> hsm
        const int pr = tid & 127, half = tid >> 7;
        ull iv[6];
#pragma unroll
        for (int ii = 0; ii < 6; ii++) iv[ii] = insm[ii * 128 + pr];
#pragma unroll
        for (int k = 0; k < 16; k++) {
            const int i = half * 16 + k;
            ull acc = sb0[i];
#pragma unroll
            for (int ii = 0; ii < 6; ii++) acc = fma2(sw0d[i * 6 + ii], iv[ii], acc);
            ull t = fma2(sa2[i], acc, sc2[i]);
            float lo, hi; unpack2(t, lo, hi);
            hsm[i * 128 + pr] = pack2(fmaxf(lo, 0.f), fmaxf(hi, 0.f));
        }
    }
    __syncthreads();

    const int wp = tid >> 5, l = tid & 31;
    ull acc[4][4];
#pragma unroll
    for (int j = 0; j < 4; j++) {
        const ull bj = sb2[wp + 8 * j];
#pragma unroll
        for (int q = 0; q < 4; q++) acc[j][q] = bj;
    }
#pragma unroll 4
    for (int i = 0; i < 32; i++) {
        ull wv[4], hv[4];
#pragma unroll
        for (int j = 0; j < 4; j++) wv[j] = sw1d[(wp + 8 * j) * 32 + i];
#pragma unroll
        for (int q = 0; q < 4; q++) hv[q] = hsm[i * 128 + l + 32 * q];
#pragma unroll
        for (int j = 0; j < 4; j++)
#pragma unroll
            for (int q = 0; q < 4; q++)
                acc[j][q] = fma2(wv[j], hv[q], acc[j][q]);
    }
#pragma unroll
    for (int j = 0; j < 4; j++) {
        const int c = wp + 8 * j;
        float v = 0.f, v2 = 0.f;
#pragma unroll
        for (int q = 0; q < 4; q++) {
            const int e = 2 * (P0 + l + 32 * q);
            *(ull*)&g_bufB[(size_t)c * CNT + e] = acc[j][q];
            float lo, hi; unpack2(acc[j][q], lo, hi);
            v  += lo + hi;
            v2 += fmaf(hi, hi, lo * lo);
        }
#pragma unroll
        for (int off = 16; off > 0; off >>= 1) {
            v  += __shfl_down_sync(0xffffffffu, v,  off);
            v2 += __shfl_down_sync(0xffffffffu, v2, off);
        }
        if (l == 0) { ssum[c] = v; ssq[c] = v2; }
    }
    __syncthreads();
    if (tid < 32) {
        atomicAdd(&g_stats[1 * 128 + tid],      ssum[tid]);
        atomicAdd(&g_stats[1 * 128 + 64 + tid], ssq[tid]);
    }
}

// ============================================================================
// 5) Layer 3 (UNCHANGED): staged GEMM + bit-exact fused k-max. Dynamic smem.
// ============================================================================
#define SMEM_L3 (32*128*8 + 2048*8 + 64*8 + 32*8 + 32*8 + 64*4 + 64*4 + 8*64*4)
__global__ void __launch_bounds__(256) l3_kernel(const float* __restrict__ w,
                                                 const float* __restrict__ bias,
                                                 const float* __restrict__ g1,
                                                 const float* __restrict__ be1)
{
    extern __shared__ char smraw[];
    ull*   hsm  = (ull*)smraw;
    ull*   swd2 = hsm + 32 * 128;
    ull*   sb2  = swd2 + 2048;
    ull*   sa2  = sb2 + 64;
    ull*   sc2  = sa2 + 32;
    float* ssum = (float*)(sc2 + 32);
    float* ssq  = ssum + 64;
    float* smax = ssq + 64;

    const int tid = threadIdx.x;
    for (int i = tid; i < 2048; i += 256) { float v = w[i]; swd2[i] = pack2(v, v); }
    if (tid < 64) { float v = bias[tid]; sb2[tid] = pack2(v, v); }
    if (tid < 32) {
        float a, c; bn_affine(1, tid, g1, be1, a, c);
        sa2[tid] = pack2(a, a); sc2[tid] = pack2(c, c);
    }
    __syncthreads();

    const int P0 = blockIdx.x * 128;
    {
        const int pr = tid & 127, half = tid >> 7;
        const int e0 = 2 * (P0 + pr);
#pragma unroll
        for (int k = 0; k < 16; k++) {
            const int i = half * 16 + k;
            ull z = *(const ull*)&g_bufB[(size_t)i * CNT + e0];
            ull t = fma2(sa2[i], z, sc2[i]);
            float lo, hi; unpack2(t, lo, hi);
            hsm[i * 128 + pr] = pack2(fmaxf(lo, 0.f), fmaxf(hi, 0.f));
        }
    }
    __syncthreads();

    const int wp = tid >> 5, l = tid & 31;
    ull acc[8][4];
#pragma unroll
    for (int j = 0; j < 8; j++) {
        const ull bj = sb2[wp + 8 * j];
#pragma unroll
        for (int q = 0; q < 4; q++) acc[j][q] = bj;
    }
#pragma unroll 2
    for (int i = 0; i < 32; i++) {
        ull wv[8], hv[4];
#pragma unroll
        for (int j = 0; j < 8; j++) wv[j] = swd2[(wp + 8 * j) * 32 + i];
#pragma unroll
        for (int q = 0; q < 4; q++) hv[q] = hsm[i * 128 + l + 32 * q];
#pragma unroll
        for (int j = 0; j < 8; j++)
#pragma unroll
            for (int q = 0; q < 4; q++)
                acc[j][q] = fma2(wv[j], hv[q], acc[j][q]);
    }
#pragma unroll
    for (int j = 0; j < 8; j++) {
        const int c = wp + 8 * j;
        float v = 0.f, v2 = 0.f;
#pragma unroll
        for (int q = 0; q < 4; q++) {
            float lo, hi; unpack2(acc[j][q], lo, hi);
            v  += lo + hi;
            v2 += fmaf(hi, hi, lo * lo);
            float mx = fmaxf(lo, hi);
#pragma unroll
            for (int off = 8; off > 0; off >>= 1)
                mx = fmaxf(mx, __shfl_down_sync(0xffffffffu, mx, off, 16));
            if ((l & 15) == 0) smax[(2 * q + (l >> 4)) * 64 + c] = mx;
        }
#pragma unroll
        for (int off = 16; off > 0; off >>= 1) {
            v  += __shfl_down_sync(0xffffffffu, v,  off);
            v2 += __shfl_down_sync(0xffffffffu, v2, off);
        }
        if (l == 0) { ssum[c] = v; ssq[c] = v2; }
    }
    __syncthreads();
    for (int idx = tid; idx < 512; idx += 256)
        g_max[(size_t)blockIdx.x * 512 + idx] = smax[idx];
    if (tid < 64) {
        atomicAdd(&g_stats[2 * 128 + tid],      ssum[tid]);
        atomicAdd(&g_stats[2 * 128 + 64 + tid], ssq[tid]);
    }
}

// ============================================================================
// 6) Finalize (UNCHANGED).
// ============================================================================
__global__ void __launch_bounds__(256) final_kernel(const float* __restrict__ g2,
                                                    const float* __restrict__ be2,
                                                    float* __restrict__ out)
{
    __shared__ float sa[64], sc[64];
    const int tid = threadIdx.x;
    if (tid < 64) {
        float a, c; bn_affine(2, tid, g2, be2, a, c);
        sa[tid] = a; sc[tid] = c;
    }
    __syncthreads();

    const int idx = blockIdx.x * 256 + tid;
    const int o = idx & 63;
    const float v = g_max[idx];
    out[OUT_XYZ_ELEMS + idx] = fmaxf(fmaf(sa[o], v, sc[o]), 0.f);
}

// ============================================================================
extern "C" void kernel_launch(void* const* d_in, const int* in_sizes, int n_in,
                              void* d_out, int out_size)
{
    const float* xyz = (const float*)d_in[0];
    const float* pts = (const float*)d_in[1];
    const float* w0  = (const float*)d_in[2];
    const float* b0  = (const float*)d_in[3];
    const float* g0  = (const float*)d_in[4];
    const float* be0 = (const float*)d_in[5];
    const float* w1  = (const float*)d_in[6];
    const float* b1  = (const float*)d_in[7];
    const float* g1  = (const float*)d_in[8];
    const float* be1 = (const float*)d_in[9];
    const float* w2  = (const float*)d_in[10];
    const float* b2  = (const float*)d_in[11];
    const float* g2  = (const float*)d_in[12];
    const float* be2 = (const float*)d_in[13];
    float* out = (float*)d_out;

    cudaFuncSetAttribute(l2_kernel,
                         cudaFuncAttributeMaxDynamicSharedMemorySize, SMEM_L2);
    cudaFuncSetAttribute(l3_kernel,
                         cudaFuncAttributeMaxDynamicSharedMemorySize, SMEM_L3);

    fps_kernel<<<BB, 512>>>(xyz);
    bq_kernel<<<(BB * SS) / 8, 256>>>(xyz, out);
    l1_kernel<<<CNT / 256, 256>>>(xyz, pts, w0, b0, out);
    l2_kernel<<<CNT / 256, 256, SMEM_L2>>>(xyz, pts, out, w0, b0, w1, b1, g0, be0);
    l3_kernel<<<CNT / 256, 256, SMEM_L3>>>(w2, b2, g1, be1);
    final_kernel<<<(BB * SS * 64) / 256, 256>>>(g2, be2, out);
}

// round 15
// speedup vs baseline: 1.0293x; 1.0293x over previous
#include <cuda_runtime.h>
#include <math.h>

#define BB 8
#define NN 8192
#define SS 2048
#define KK 32
#define CNT (BB*SS*KK)          // 524288 elements per layer
#define OUT_XYZ_ELEMS (BB*SS*3) // 49152

typedef unsigned long long ull;

// ---------------- scratch (static device memory; no runtime allocation) ----
__device__ float g_bufA[(size_t)CNT * 32];  // 64 MB : z1 (32ch), channel-major [c][e]
__device__ float g_bufB[(size_t)CNT * 32];  // 64 MB : z2 (32ch), channel-major
__device__ float g_max[(size_t)BB * SS * 64]; // 4 MB : per-(b,s) max_k z3, [bs][o]
__device__ int   g_fps[BB * SS];
__device__ int   g_ball[BB * SS * KK];
__device__ float g_stats[3 * 128];          // per layer: [0..63]=sum, [64..127]=sumsq

// ---------------- packed f32x2 helpers (sm_103a) ---------------------------
__device__ __forceinline__ ull pack2(float lo, float hi) {
    ull r; asm("mov.b64 %0,{%1,%2};" : "=l"(r) : "f"(lo), "f"(hi)); return r;
}
__device__ __forceinline__ void unpack2(ull v, float& lo, float& hi) {
    asm("mov.b64 {%0,%1},%2;" : "=f"(lo), "=f"(hi) : "l"(v));
}
__device__ __forceinline__ ull add2(ull a, ull b) {
    ull r; asm("add.rn.f32x2 %0,%1,%2;" : "=l"(r) : "l"(a), "l"(b)); return r;
}
__device__ __forceinline__ ull mul2(ull a, ull b) {
    ull r; asm("mul.rn.f32x2 %0,%1,%2;" : "=l"(r) : "l"(a), "l"(b)); return r;
}
__device__ __forceinline__ ull fma2(ull a, ull b, ull c) {
    ull r; asm("fma.rn.f32x2 %0,%1,%2,%3;" : "=l"(r) : "l"(a), "l"(b), "l"(c)); return r;
}

// ============================================================================
// 1) Farthest point sampling (UNCHANGED — banked structure).
// ============================================================================
__global__ void __launch_bounds__(512) fps_kernel(const float* __restrict__ xyz)
{
    const int b = blockIdx.x;
    const float* base = xyz + (size_t)b * NN * 3;
    const int t = threadIdx.x;
    const int lane = t & 31, wid = t >> 5;

    ull px[8], py[8], pz[8];
    float dd[16];
#pragma unroll
    for (int k = 0; k < 8; k++) {
        const int p0 = t + (2 * k) * 512;
        const int p1 = t + (2 * k + 1) * 512;
        px[k] = pack2(base[3 * p0 + 0], base[3 * p1 + 0]);
        py[k] = pack2(base[3 * p0 + 1], base[3 * p1 + 1]);
        pz[k] = pack2(base[3 * p0 + 2], base[3 * p1 + 2]);
    }
#pragma unroll
    for (int j = 0; j < 16; j++) dd[j] = 1e10f;

    __shared__ unsigned sdist[16];
    __shared__ unsigned sidxs[3];
    if (t < 3) sidxs[t] = 0xffffffffu;
    __syncthreads();

    float cx = base[0], cy = base[1], cz = base[2];
    int cur = 0;
    int slot = 0, nslot = 1, rslot = 2;

    for (int it = 0; it < SS; it++) {
        if (t == 0) {
            g_fps[b * SS + it] = cur;
            sidxs[nslot] = 0xffffffffu;
        }
        const ull ncx = pack2(-cx, -cx);
        const ull ncy = pack2(-cy, -cy);
        const ull ncz = pack2(-cz, -cz);

        float m0 = 0.f, m1 = 0.f;
#pragma unroll
        for (int k = 0; k < 8; k++) {
            ull dx = add2(px[k], ncx);
            ull dy = add2(py[k], ncy);
            ull dz = add2(pz[k], ncz);
            ull d2 = mul2(dx, dx);
            d2 = fma2(dy, dy, d2);
            d2 = fma2(dz, dz, d2);
            float dlo, dhi; unpack2(d2, dlo, dhi);
            const float nlo = fminf(dd[2 * k],     dlo);
            const float nhi = fminf(dd[2 * k + 1], dhi);
            dd[2 * k]     = nlo;
            dd[2 * k + 1] = nhi;
            m0 = fmaxf(m0, nlo);
            m1 = fmaxf(m1, nhi);
        }
        const float m = fmaxf(m0, m1);
        const unsigned mb   = __float_as_uint(m);
        const unsigned wmax = __reduce_max_sync(0xffffffffu, mb);
        if (lane == 0) sdist[wid] = wmax;
        __syncthreads();

        const unsigned bmax = __reduce_max_sync(0xffffffffu, sdist[lane & 15]);

        if (wmax == bmax) {
            unsigned bi = 0xffffffffu;
            if (mb == bmax) {
#pragma unroll
                for (int j = 15; j >= 0; j--)
                    if (__float_as_uint(dd[j]) == bmax) bi = (unsigned)(t + j * 512);
            }
            const unsigned rid = __reduce_min_sync(0xffffffffu, bi);
            if (lane == 0) atomicMin(&sidxs[slot], rid);
        }
        __syncthreads();

        cur = (int)sidxs[slot];
        cx = base[3 * cur + 0];
        cy = base[3 * cur + 1];
        cz = base[3 * cur + 2];

        const int tmp = slot; slot = nslot; nslot = rslot; rslot = tmp;
    }
}

// ============================================================================
// 2) new_xyz gather + ball query (round-13 form, UNCHANGED).
// ============================================================================
#define TPTS 1024
__global__ void __launch_bounds__(256) bq_kernel(const float* __restrict__ xyz,
                                                 float* __restrict__ newxyz)
{
    const int tid = threadIdx.x;
    if (blockIdx.x == 0) {
        for (int i = tid; i < 384; i += 256) g_stats[i] = 0.f;
    }

    const int warp = tid >> 5, lane = tid & 31;
    const int gs = blockIdx.x * 8 + warp;
    const int b  = gs >> 11;
    const float* base = xyz + (size_t)b * NN * 3;

    __shared__ float spts[TPTS * 3];
    __shared__ int   sidx[8][KK];
    __shared__ int   sdone;
    if (tid == 0) sdone = 0;

    const int ci = g_fps[gs];
    const float cx = base[3 * ci + 0];
    const float cy = base[3 * ci + 1];
    const float cz = base[3 * ci + 2];
    if (lane < 3) newxyz[(size_t)gs * 3 + lane] = base[3 * ci + lane];

    const float r2 = (float)(0.2 * 0.2);
    int cnt = 0, first = 0x7fffffff;
    bool done = false;

    for (int tile = 0; tile < NN; tile += TPTS) {
        __syncthreads();
        if (sdone == 8) break;
        for (int i = tid; i < TPTS * 3; i += 256)
            spts[i] = base[(size_t)tile * 3 + i];
        __syncthreads();

        if (!done) {
            for (int p0 = 0; p0 < TPTS; p0 += 32) {
                const int p = p0 + lane;
                float dx = spts[3 * p + 0] - cx;
                float dy = spts[3 * p + 1] - cy;
                float dz = spts[3 * p + 2] - cz;
                float sq = dx * dx + dy * dy + dz * dz;
                bool  in = !(sq > r2);
                unsigned mm = __ballot_sync(0xffffffffu, in);
                if (in) {
                    int pos = cnt + __popc(mm & ((1u << lane) - 1u));
                    if (pos < KK) sidx[warp][pos] = tile + p;
                    if (pos == 0) first = tile + p;
                }
                cnt += __popc(mm);
                if (cnt >= KK) break;
            }
            if (cnt >= KK) {
                done = true;
                if (lane == 0) atomicAdd(&sdone, 1);
            }
        }
    }
#pragma unroll
    for (int off = 16; off > 0; off >>= 1)
        first = min(first, __shfl_down_sync(0xffffffffu, first, off));
    first = __shfl_sync(0xffffffffu, first, 0);

    const int cc = cnt < KK ? cnt : KK;
    const int v  = (lane < cc) ? sidx[warp][lane] : first;
    g_ball[(size_t)gs * KK + lane] = v;
}

// BN affine from stats
__device__ __forceinline__ void bn_affine(int L, int c,
                                          const float* __restrict__ g,
                                          const float* __restrict__ be,
                                          float& a, float& cc)
{
    const float inv  = 1.f / (float)CNT;
    const float mean = g_stats[L * 128 + c] * inv;
    const float var  = g_stats[L * 128 + 64 + c] * inv - mean * mean;
    a  = g[c] * rsqrtf(var + 1e-5f);
    cc = be[c] - mean * a;
}

// ============================================================================
// 3) Layer 1 (round-13 structure + 128-bit weight LDS): gather to smem,
//    warp-per-channel-group conv, z1 write, single-owner stats.
// ============================================================================
__global__ void __launch_bounds__(256) l1_kernel(const float* __restrict__ xyz,
                                                 const float* __restrict__ pts,
                                                 const float* __restrict__ w,
                                                 const float* __restrict__ bias,
                                                 const float* __restrict__ newxyz)
{
    __shared__ __align__(16) ull hsm[6][128];
    __shared__ __align__(16) ull swd2[192];
    __shared__ ull   sb2[32];
    __shared__ float ssum[32], ssq[32];
    const int tid = threadIdx.x;
    if (tid < 192) { float v = w[tid]; swd2[tid] = pack2(v, v); }
    if (tid < 32)  { float v = bias[tid]; sb2[tid] = pack2(v, v); }
    __syncthreads();

    const int P0 = blockIdx.x * 128;
    if (tid < 128) {
        const int e0 = 2 * (P0 + tid);
        const int bs = e0 >> 5;
        const int b  = bs >> 11;
        const int2 pp = *(const int2*)&g_ball[e0];
        const float* xb = xyz + (size_t)b * NN * 3;
        const float* pb = pts + (size_t)b * NN * 3;
        const float nx = newxyz[(size_t)bs * 3 + 0];
        const float ny = newxyz[(size_t)bs * 3 + 1];
        const float nz = newxyz[(size_t)bs * 3 + 2];
        hsm[0][tid] = pack2(xb[3 * pp.x + 0] - nx, xb[3 * pp.y + 0] - nx);
        hsm[1][tid] = pack2(xb[3 * pp.x + 1] - ny, xb[3 * pp.y + 1] - ny);
        hsm[2][tid] = pack2(xb[3 * pp.x + 2] - nz, xb[3 * pp.y + 2] - nz);
        hsm[3][tid] = pack2(pb[3 * pp.x + 0], pb[3 * pp.y + 0]);
        hsm[4][tid] = pack2(pb[3 * pp.x + 1], pb[3 * pp.y + 1]);
        hsm[5][tid] = pack2(pb[3 * pp.x + 2], pb[3 * pp.y + 2]);
    }
    __syncthreads();

    const int wp = tid >> 5, l = tid & 31;
    ull acc[4][4];
#pragma unroll
    for (int j = 0; j < 4; j++) {
        const ull bj = sb2[wp + 8 * j];
#pragma unroll
        for (int q = 0; q < 4; q++) acc[j][q] = bj;
    }
#pragma unroll
    for (int i2 = 0; i2 < 3; i2++) {           // i = 2*i2, 2*i2+1
        ulonglong2 wv[4];
        ull hva[4], hvb[4];
#pragma unroll
        for (int j = 0; j < 4; j++)
            wv[j] = *(const ulonglong2*)&swd2[(wp + 8 * j) * 6 + 2 * i2];
#pragma unroll
        for (int q = 0; q < 4; q++) {
            hva[q] = hsm[2 * i2][l + 32 * q];
            hvb[q] = hsm[2 * i2 + 1][l + 32 * q];
        }
#pragma unroll
        for (int j = 0; j < 4; j++)
#pragma unroll
            for (int q = 0; q < 4; q++) {
                acc[j][q] = fma2(wv[j].x, hva[q], acc[j][q]);
                acc[j][q] = fma2(wv[j].y, hvb[q], acc[j][q]);
            }
    }
#pragma unroll
    for (int j = 0; j < 4; j++) {
        const int c = wp + 8 * j;
        float v = 0.f, v2 = 0.f;
#pragma unroll
        for (int q = 0; q < 4; q++) {
            const int e = 2 * (P0 + l + 32 * q);
            *(ull*)&g_bufA[(size_t)c * CNT + e] = acc[j][q];
            float lo, hi; unpack2(acc[j][q], lo, hi);
            v  += lo + hi;
            v2 += fmaf(hi, hi, lo * lo);
        }
#pragma unroll
        for (int off = 16; off > 0; off >>= 1) {
            v  += __shfl_down_sync(0xffffffffu, v,  off);
            v2 += __shfl_down_sync(0xffffffffu, v2, off);
        }
        if (l == 0) { ssum[c] = v; ssq[c] = v2; }
    }
    __syncthreads();
    if (tid < 32) {
        atomicAdd(&g_stats[0 * 128 + tid],      ssum[tid]);
        atomicAdd(&g_stats[0 * 128 + 64 + tid], ssq[tid]);
    }
}

// ============================================================================
// 4) Layer 2 (round-13 structure + 128-bit staging/weight loads).
// ============================================================================
__global__ void __launch_bounds__(256) l2_kernel(const float* __restrict__ w,
                                                 const float* __restrict__ bias,
                                                 const float* __restrict__ g0,
                                                 const float* __restrict__ be0)
{
    __shared__ __align__(16) ull hsm[32][128];     // 32 KB
    __shared__ __align__(16) ull swd2[1024];       // 8 KB
    __shared__ ull   sb2[32], sa2[32], sc2[32];
    __shared__ float ssum[32], ssq[32];
    const int tid = threadIdx.x;
    for (int i = tid; i < 1024; i += 256) { float v = w[i]; swd2[i] = pack2(v, v); }
    if (tid < 32) {
        float v = bias[tid]; sb2[tid] = pack2(v, v);
        float a, c; bn_affine(0, tid, g0, be0, a, c);
        sa2[tid] = pack2(a, a); sc2[tid] = pack2(c, c);
    }
    __syncthreads();

    const int P0 = blockIdx.x * 128;
    {   // stage: thread covers one quad (2 pairs) for 8 channels; LDG.128
        const int qd = tid & 63, grp = tid >> 6;
        const int e0 = 2 * P0 + 4 * qd;
#pragma unroll
        for (int k = 0; k < 8; k++) {
            const int i = grp * 8 + k;
            ulonglong2 z = *(const ulonglong2*)&g_bufA[(size_t)i * CNT + e0];
            ull t0 = fma2(sa2[i], z.x, sc2[i]);
            ull t1 = fma2(sa2[i], z.y, sc2[i]);
            float l0, h0, l1, h1; unpack2(t0, l0, h0); unpack2(t1, l1, h1);
            ulonglong2 hq;
            hq.x = pack2(fmaxf(l0, 0.f), fmaxf(h0, 0.f));
            hq.y = pack2(fmaxf(l1, 0.f), fmaxf(h1, 0.f));
            *(ulonglong2*)&hsm[i][2 * qd] = hq;
        }
    }
    __syncthreads();

    const int wp = tid >> 5, l = tid & 31;
    ull acc[4][4];
#pragma unroll
    for (int j = 0; j < 4; j++) {
        const ull bj = sb2[wp + 8 * j];
#pragma unroll
        for (int q = 0; q < 4; q++) acc[j][q] = bj;
    }
#pragma unroll 2
    for (int i2 = 0; i2 < 16; i2++) {          // i = 2*i2, 2*i2+1
        ulonglong2 wv[4];
        ull hva[4], hvb[4];
#pragma unroll
        for (int j = 0; j < 4; j++)
            wv[j] = *(const ulonglong2*)&swd2[(wp + 8 * j) * 32 + 2 * i2];
#pragma unroll
        for (int q = 0; q < 4; q++) {
            hva[q] = hsm[2 * i2][l + 32 * q];
            hvb[q] = hsm[2 * i2 + 1][l + 32 * q];
        }
#pragma unroll
        for (int j = 0; j < 4; j++)
#pragma unroll
            for (int q = 0; q < 4; q++) {
                acc[j][q] = fma2(wv[j].x, hva[q], acc[j][q]);
                acc[j][q] = fma2(wv[j].y, hvb[q], acc[j][q]);
            }
    }
#pragma unroll
    for (int j = 0; j < 4; j++) {
        const int c = wp + 8 * j;
        float v = 0.f, v2 = 0.f;
#pragma unroll
        for (int q = 0; q < 4; q++) {
            const int e = 2 * (P0 + l + 32 * q);
            *(ull*)&g_bufB[(size_t)c * CNT + e] = acc[j][q];
            float lo, hi; unpack2(acc[j][q], lo, hi);
            v  += lo + hi;
            v2 += fmaf(hi, hi, lo * lo);
        }
#pragma unroll
        for (int off = 16; off > 0; off >>= 1) {
            v  += __shfl_down_sync(0xffffffffu, v,  off);
            v2 += __shfl_down_sync(0xffffffffu, v2, off);
        }
        if (l == 0) { ssum[c] = v; ssq[c] = v2; }
    }
    __syncthreads();
    if (tid < 32) {
        atomicAdd(&g_stats[1 * 128 + tid],      ssum[tid]);
        atomicAdd(&g_stats[1 * 128 + 64 + tid], ssq[tid]);
    }
}

// ============================================================================
// 5) Layer 3 (round-13 structure + 128-bit staging/weight loads) with the
//    bit-exact fused k-max. Dynamic smem.
// ============================================================================
#define SMEM_L3 (32*128*8 + 2048*8 + 64*8 + 32*8 + 32*8 + 64*4 + 64*4 + 8*64*4)
__global__ void __launch_bounds__(256) l3_kernel(const float* __restrict__ w,
                                                 const float* __restrict__ bias,
                                                 const float* __restrict__ g1,
                                                 const float* __restrict__ be1)
{
    extern __shared__ char smraw[];
    ull*   hsm  = (ull*)smraw;            // [32][128], base 16B-aligned
    ull*   swd2 = hsm + 32 * 128;         // [2048], offset 32768 (16B-aligned)
    ull*   sb2  = swd2 + 2048;
    ull*   sa2  = sb2 + 64;
    ull*   sc2  = sa2 + 32;
    float* ssum = (float*)(sc2 + 32);
    float* ssq  = ssum + 64;
    float* smax = ssq + 64;

    const int tid = threadIdx.x;
    for (int i = tid; i < 2048; i += 256) { float v = w[i]; swd2[i] = pack2(v, v); }
    if (tid < 64) { float v = bias[tid]; sb2[tid] = pack2(v, v); }
    if (tid < 32) {
        float a, c; bn_affine(1, tid, g1, be1, a, c);
        sa2[tid] = pack2(a, a); sc2[tid] = pack2(c, c);
    }
    __syncthreads();

    const int P0 = blockIdx.x * 128;
    {
        const int qd = tid & 63, grp = tid >> 6;
        const int e0 = 2 * P0 + 4 * qd;
#pragma unroll
        for (int k = 0; k < 8; k++) {
            const int i = grp * 8 + k;
            ulonglong2 z = *(const ulonglong2*)&g_bufB[(size_t)i * CNT + e0];
            ull t0 = fma2(sa2[i], z.x, sc2[i]);
            ull t1 = fma2(sa2[i], z.y, sc2[i]);
            float l0, h0, l1, h1; unpack2(t0, l0, h0); unpack2(t1, l1, h1);
            ulonglong2 hq;
            hq.x = pack2(fmaxf(l0, 0.f), fmaxf(h0, 0.f));
            hq.y = pack2(fmaxf(l1, 0.f), fmaxf(h1, 0.f));
            *(ulonglong2*)&hsm[i * 128 + 2 * qd] = hq;
        }
    }
    __syncthreads();

    const int wp = tid >> 5, l = tid & 31;
    ull acc[8][4];
#pragma unroll
    for (int j = 0; j < 8; j++) {
        const ull bj = sb2[wp + 8 * j];
#pragma unroll
        for (int q = 0; q < 4; q++) acc[j][q] = bj;
    }
#pragma unroll 1
    for (int i2 = 0; i2 < 16; i2++) {
        ulonglong2 wv[8];
        ull hva[4], hvb[4];
#pragma unroll
        for (int j = 0; j < 8; j++)
            wv[j] = *(const ulonglong2*)&swd2[(wp + 8 * j) * 32 + 2 * i2];
#pragma unroll
        for (int q = 0; q < 4; q++) {
            hva[q] = hsm[(2 * i2) * 128 + l + 32 * q];
            hvb[q] = hsm[(2 * i2 + 1) * 128 + l + 32 * q];
        }
#pragma unroll
        for (int j = 0; j < 8; j++)
#pragma unroll
            for (int q = 0; q < 4; q++) {
                acc[j][q] = fma2(wv[j].x, hva[q], acc[j][q]);
                acc[j][q] = fma2(wv[j].y, hvb[q], acc[j][q]);
            }
    }
#pragma unroll
    for (int j = 0; j < 8; j++) {
        const int c = wp + 8 * j;
        float v = 0.f, v2 = 0.f;
#pragma unroll
        for (int q = 0; q < 4; q++) {
            float lo, hi; unpack2(acc[j][q], lo, hi);
            v  += lo + hi;
            v2 += fmaf(hi, hi, lo * lo);
            float mx = fmaxf(lo, hi);
#pragma unroll
            for (int off = 8; off > 0; off >>= 1)
                mx = fmaxf(mx, __shfl_down_sync(0xffffffffu, mx, off, 16));
            if ((l & 15) == 0) smax[(2 * q + (l >> 4)) * 64 + c] = mx;
        }
#pragma unroll
        for (int off = 16; off > 0; off >>= 1) {
            v  += __shfl_down_sync(0xffffffffu, v,  off);
            v2 += __shfl_down_sync(0xffffffffu, v2, off);
        }
        if (l == 0) { ssum[c] = v; ssq[c] = v2; }
    }
    __syncthreads();
    for (int idx = tid; idx < 512; idx += 256)
        g_max[(size_t)blockIdx.x * 512 + idx] = smax[idx];
    if (tid < 64) {
        atomicAdd(&g_stats[2 * 128 + tid],      ssum[tid]);
        atomicAdd(&g_stats[2 * 128 + 64 + tid], ssq[tid]);
    }
}

// ============================================================================
// 6) Finalize (UNCHANGED).
// ============================================================================
__global__ void __launch_bounds__(256) final_kernel(const float* __restrict__ g2,
                                                    const float* __restrict__ be2,
                                                    float* __restrict__ out)
{
    __shared__ float sa[64], sc[64];
    const int tid = threadIdx.x;
    if (tid < 64) {
        float a, c; bn_affine(2, tid, g2, be2, a, c);
        sa[tid] = a; sc[tid] = c;
    }
    __syncthreads();

    const int idx = blockIdx.x * 256 + tid;
    const int o = idx & 63;
    const float v = g_max[idx];
    out[OUT_XYZ_ELEMS + idx] = fmaxf(fmaf(sa[o], v, sc[o]), 0.f);
}

// ============================================================================
extern "C" void kernel_launch(void* const* d_in, const int* in_sizes, int n_in,
                              void* d_out, int out_size)
{
    const float* xyz = (const float*)d_in[0];
    const float* pts = (const float*)d_in[1];
    const float* w0  = (const float*)d_in[2];
    const float* b0  = (const float*)d_in[3];
    const float* g0  = (const float*)d_in[4];
    const float* be0 = (const float*)d_in[5];
    const float* w1  = (const float*)d_in[6];
    const float* b1  = (const float*)d_in[7];
    const float* g1  = (const float*)d_in[8];
    const float* be1 = (const float*)d_in[9];
    const float* w2  = (const float*)d_in[10];
    const float* b2  = (const float*)d_in[11];
    const float* g2  = (const float*)d_in[12];
    const float* be2 = (const float*)d_in[13];
    float* out = (float*)d_out;

    cudaFuncSetAttribute(l3_kernel,
                         cudaFuncAttributeMaxDynamicSharedMemorySize, SMEM_L3);

    fps_kernel<<<BB, 512>>>(xyz);
    bq_kernel<<<(BB * SS) / 8, 256>>>(xyz, out);
    l1_kernel<<<CNT / 256, 256>>>(xyz, pts, w0, b0, out);
    l2_kernel<<<CNT / 256, 256>>>(w1, b1, g0, be0);
    l3_kernel<<<CNT / 256, 256, SMEM_L3>>>(w2, b2, g1, be1);
    final_kernel<<<(BB * SS * 64) / 256, 256>>>(g2, be2, out);
}